// round 2
// baseline (speedup 1.0000x reference)
#include <cuda_runtime.h>
#include <cuda_bf16.h>

// FlashAttention B=4,H=12,S=4096,D=64, TILE=128, fp32.
// Faithfully reproduces the reference's non-standard online-softmax recurrence
// (extra cur_scale = exp(cur_max - new_max) factor per tile, folded as
//  p = exp(s + cur_max - 2*new_max)).
//
// SIMT kernel using packed fma.rn.f32x2 (sm_103a FFMA2), transposed+swizzled
// smem operand layouts so packed pairs load directly from shared memory.

#define SDIM 4096
#define DDIM 64
#define QTILE 128
#define NKT 32

static const int SMEM_FLOATS = 64*128 /*sQT*/ + 64*128 /*sKT*/ + 128*64 /*sV*/ + 128*128 /*sPT*/;
static const int SMEM_BYTES  = SMEM_FLOATS * 4; // 163840

typedef unsigned long long ull;

__device__ __forceinline__ ull pk2(float x) {
    ull r; asm("mov.b64 %0, {%1, %1};" : "=l"(r) : "f"(x)); return r;
}
__device__ __forceinline__ ull pkxy(float x, float y) {
    ull r; asm("mov.b64 %0, {%1, %2};" : "=l"(r) : "f"(x), "f"(y)); return r;
}
__device__ __forceinline__ void fma2(ull &d, ull a, ull b) {
    asm("fma.rn.f32x2 %0, %1, %2, %0;" : "+l"(d) : "l"(a), "l"(b));
}
__device__ __forceinline__ void mul2(ull &d, ull a) {
    asm("mul.rn.f32x2 %0, %0, %1;" : "+l"(d) : "l"(a));
}
__device__ __forceinline__ float2 upk(ull v) {
    float2 f; asm("mov.b64 {%0, %1}, %2;" : "=f"(f.x), "=f"(f.y) : "l"(v)); return f;
}

__global__ void __launch_bounds__(256, 1)
fa_kernel(const float* __restrict__ Q, const float* __restrict__ K,
          const float* __restrict__ V, float* __restrict__ O)
{
    extern __shared__ float sm[];
    float* sQT = sm;                    // [64][128] transposed, swizzled
    float* sKT = sm + 64*128;           // [64][128] transposed, swizzled
    float* sV  = sm + 2*64*128;         // [128][64] natural
    float* sPT = sm + 3*64*128;         // [128][128] P transposed, swizzled

    const int tid = threadIdx.x;
    const int tx  = tid & 15;           // 0..15
    const int ty  = tid >> 4;           // 0..15
    const int r0  = ty << 3;            // 8 q-rows per thread

    const int qt = blockIdx.x & 31;
    const int bh = blockIdx.x >> 5;

    const float* Qg = Q + ((long)bh * SDIM + qt * QTILE) * DDIM;
    const float* Kg = K + (long)bh * SDIM * DDIM;
    const float* Vg = V + (long)bh * SDIM * DDIM;
    float*       Og = O + ((long)bh * SDIM + qt * QTILE) * DDIM;

    const float scale = 0.125f; // 1/sqrt(64)

    // ---- Load Q tile transposed into sQT (pre-scaled) ----
    // element (k=d, c=row): offset = k*128 + ((c>>2)^((k>>2)&7))*4 + (c&3)
    #pragma unroll
    for (int i = 0; i < 8; i++) {
        int lin = i * 256 + tid;        // float4 index, 0..2047
        int row = lin >> 4;             // 0..127
        int k0  = (lin & 15) << 2;      // 0..60
        float4 v = *(const float4*)(Qg + row * DDIM + k0);
        int off = (((row >> 2) ^ ((k0 >> 2) & 7)) << 2) | (row & 3);
        sQT[(k0 + 0) * 128 + off] = v.x * scale;
        sQT[(k0 + 1) * 128 + off] = v.y * scale;
        sQT[(k0 + 2) * 128 + off] = v.z * scale;
        sQT[(k0 + 3) * 128 + off] = v.w * scale;
    }

    // ---- Persistent per-thread state ----
    ull   o[4][4];                      // O accum: row-pairs (r0+2p, r0+2p+1) x 4 d-cols
    float m_i[8], ss_i[8];
    #pragma unroll
    for (int p = 0; p < 4; p++)
        #pragma unroll
        for (int d = 0; d < 4; d++) o[p][d] = 0ULL;
    #pragma unroll
    for (int r = 0; r < 8; r++) { m_i[r] = -INFINITY; ss_i[r] = 0.0f; }

    for (int kt = 0; kt < NKT; kt++) {
        __syncthreads();  // prior iter done reading sKT/sV/sPT

        // ---- Load K tile transposed, V tile natural ----
        const float* Kt = Kg + kt * QTILE * DDIM;
        const float* Vt = Vg + kt * QTILE * DDIM;
        #pragma unroll
        for (int i = 0; i < 8; i++) {
            int lin = i * 256 + tid;
            int row = lin >> 4;
            int k0  = (lin & 15) << 2;
            float4 v = *(const float4*)(Kt + row * DDIM + k0);
            int off = (((row >> 2) ^ ((k0 >> 2) & 7)) << 2) | (row & 3);
            sKT[(k0 + 0) * 128 + off] = v.x;
            sKT[(k0 + 1) * 128 + off] = v.y;
            sKT[(k0 + 2) * 128 + off] = v.z;
            sKT[(k0 + 3) * 128 + off] = v.w;
        }
        #pragma unroll
        for (int i = 0; i < 8; i++) {
            int lin = i * 256 + tid;
            int row = lin >> 4;
            int dg  = (lin & 15) << 2;
            *(float4*)(sV + row * DDIM + dg) = *(const float4*)(Vt + row * DDIM + dg);
        }
        __syncthreads();

        // ---- Score GEMM: acc[p][j], row-pairs x 8 cols ----
        // cols: j<4 -> 4*tx+j ; j>=4 -> 64+4*tx+(j-4)
        ull acc[4][8];
        #pragma unroll
        for (int p = 0; p < 4; p++)
            #pragma unroll
            for (int j = 0; j < 8; j++) acc[p][j] = 0ULL;

        for (int k4 = 0; k4 < 16; k4++) {
            int key = k4 & 7;
            #pragma unroll
            for (int kk = 0; kk < 3 + 1; kk++) {
                const float* qp = sQT + ((k4 << 2) + kk) * 128;
                const float* kp = sKT + ((k4 << 2) + kk) * 128;
                ulonglong2 A0 = *(const ulonglong2*)(qp + ((( (ty << 1)     ) ^ key) << 2));
                ulonglong2 A1 = *(const ulonglong2*)(qp + ((( (ty << 1) | 1 ) ^ key) << 2));
                float4 b0 = *(const float4*)(kp + ((tx ^ key) << 2));
                float4 b1 = *(const float4*)(kp + ((tx ^ key) << 2) + 64);
                ull a0 = A0.x, a1 = A0.y, a2 = A1.x, a3 = A1.y;
                ull bb[8];
                bb[0] = pk2(b0.x); bb[1] = pk2(b0.y); bb[2] = pk2(b0.z); bb[3] = pk2(b0.w);
                bb[4] = pk2(b1.x); bb[5] = pk2(b1.y); bb[6] = pk2(b1.z); bb[7] = pk2(b1.w);
                #pragma unroll
                for (int j = 0; j < 8; j++) {
                    fma2(acc[0][j], a0, bb[j]);
                    fma2(acc[1][j], a1, bb[j]);
                    fma2(acc[2][j], a2, bb[j]);
                    fma2(acc[3][j], a3, bb[j]);
                }
            }
        }

        // ---- Softmax (reference recurrence, cur_scale folded) ----
        float s[8][8];
        #pragma unroll
        for (int p = 0; p < 4; p++)
            #pragma unroll
            for (int j = 0; j < 8; j++) {
                float2 f = upk(acc[p][j]);
                s[2*p][j] = f.x; s[2*p+1][j] = f.y;
            }

        float osc[8];
        #pragma unroll
        for (int r = 0; r < 8; r++) {
            float mx = s[r][0];
            #pragma unroll
            for (int j = 1; j < 8; j++) mx = fmaxf(mx, s[r][j]);
            mx = fmaxf(mx, __shfl_xor_sync(0xffffffffu, mx, 1));
            mx = fmaxf(mx, __shfl_xor_sync(0xffffffffu, mx, 2));
            mx = fmaxf(mx, __shfl_xor_sync(0xffffffffu, mx, 4));
            mx = fmaxf(mx, __shfl_xor_sync(0xffffffffu, mx, 8));
            float nm  = fmaxf(m_i[r], mx);
            float adj = mx - 2.0f * nm;       // fold cur_scale into exponent
            float rs = 0.0f;
            #pragma unroll
            for (int j = 0; j < 8; j++) {
                float e = __expf(s[r][j] + adj);
                s[r][j] = e;
                rs += e;
            }
            rs += __shfl_xor_sync(0xffffffffu, rs, 1);
            rs += __shfl_xor_sync(0xffffffffu, rs, 2);
            rs += __shfl_xor_sync(0xffffffffu, rs, 4);
            rs += __shfl_xor_sync(0xffffffffu, rs, 8);
            osc[r]  = __expf(m_i[r] - nm);
            ss_i[r] = ss_i[r] * osc[r] + rs;
            m_i[r]  = nm;
        }

        // rescale O accumulators
        #pragma unroll
        for (int p = 0; p < 4; p++) {
            ull op = pkxy(osc[2*p], osc[2*p+1]);
            #pragma unroll
            for (int d = 0; d < 4; d++) mul2(o[p][d], op);
        }

        // ---- Store P transposed into sPT (swizzled) ----
        {
            int key2 = tx & 7;
            #pragma unroll
            for (int j = 0; j < 8; j++) {
                int c = (j < 4) ? (tx * 4 + j) : (64 + tx * 4 + (j - 4));
                float* base = sPT + c * 128;
                *(float4*)(base + ((( (ty << 1)     ) ^ key2) << 2)) =
                    make_float4(s[0][j], s[1][j], s[2][j], s[3][j]);
                *(float4*)(base + ((( (ty << 1) | 1 ) ^ key2) << 2)) =
                    make_float4(s[4][j], s[5][j], s[6][j], s[7][j]);
            }
        }
        __syncthreads();

        // ---- PV GEMM: O[rowpair][d] += P^T pairs * V ----
        for (int c4 = 0; c4 < 32; c4++) {
            int key = c4 & 7;
            #pragma unroll
            for (int cc = 0; cc < 4; cc++) {
                int c = (c4 << 2) + cc;
                const float* pb = sPT + c * 128;
                ulonglong2 A0 = *(const ulonglong2*)(pb + ((( (ty << 1)     ) ^ key) << 2));
                ulonglong2 A1 = *(const ulonglong2*)(pb + ((( (ty << 1) | 1 ) ^ key) << 2));
                float4 bv = *(const float4*)(sV + c * DDIM + (tx << 2));
                ull b0 = pk2(bv.x), b1 = pk2(bv.y), b2 = pk2(bv.z), b3 = pk2(bv.w);
                ull a0 = A0.x, a1 = A0.y, a2 = A1.x, a3 = A1.y;
                fma2(o[0][0], a0, b0); fma2(o[0][1], a0, b1); fma2(o[0][2], a0, b2); fma2(o[0][3], a0, b3);
                fma2(o[1][0], a1, b0); fma2(o[1][1], a1, b1); fma2(o[1][2], a1, b2); fma2(o[1][3], a1, b3);
                fma2(o[2][0], a2, b0); fma2(o[2][1], a2, b1); fma2(o[2][2], a2, b2); fma2(o[2][3], a2, b3);
                fma2(o[3][0], a3, b0); fma2(o[3][1], a3, b1); fma2(o[3][2], a3, b2); fma2(o[3][3], a3, b3);
            }
        }
    }

    // ---- Finalize: divide by ssum, write out ----
    #pragma unroll
    for (int p = 0; p < 4; p++) {
        float2 f0 = upk(o[p][0]);
        float2 f1 = upk(o[p][1]);
        float2 f2 = upk(o[p][2]);
        float2 f3 = upk(o[p][3]);
        float invA = 1.0f / ss_i[2*p];
        float invB = 1.0f / ss_i[2*p+1];
        float4 wa = make_float4(f0.x * invA, f1.x * invA, f2.x * invA, f3.x * invA);
        float4 wb = make_float4(f0.y * invB, f1.y * invB, f2.y * invB, f3.y * invB);
        *(float4*)(Og + (r0 + 2*p    ) * DDIM + (tx << 2)) = wa;
        *(float4*)(Og + (r0 + 2*p + 1) * DDIM + (tx << 2)) = wb;
    }
}

extern "C" void kernel_launch(void* const* d_in, const int* in_sizes, int n_in,
                              void* d_out, int out_size)
{
    const float* Q = (const float*)d_in[0];
    const float* K = (const float*)d_in[1];
    const float* V = (const float*)d_in[2];
    float* O = (float*)d_out;

    cudaFuncSetAttribute(fa_kernel, cudaFuncAttributeMaxDynamicSharedMemorySize, SMEM_BYTES);
    fa_kernel<<<48 * 32, 256, SMEM_BYTES>>>(Q, K, V, O);
}

// round 5
// speedup vs baseline: 5.4124x; 5.4124x over previous
#include <cuda_runtime.h>
#include <cuda_fp16.h>
#include <cstdint>

// FlashAttention B=4,H=12,S=4096,D=64, TILE=128, fp32 in/out.
// mma.sync m16n8k16 fp16 (plain sm_103 target — no tcgen05 available).
// Reference recurrence kept exactly: p = exp(s + mx - 2*nm),
// O = O*exp(m-nm) + P@V, ssum = ssum*exp(m-nm) + rowsum(P).
// All softmax math in base-2 domain (Q pre-scaled by 0.125*log2(e)).

#define S_LEN 4096
#define NKT   32
#define BH_N  48

#define ROWB  144           // padded row: 72 halves = 144 bytes (64 data + 8 pad)
#define TILEB (128*ROWB)    // 18432 bytes per tile
#define QOFF  0
#define KOFF  18432
#define VOFF  (18432*3)     // 55296
#define SMEM_MAIN (18432*5) // 92160

// fp16 pre-converted tensors
__device__ __align__(128) __half g_Qh[(size_t)BH_N * S_LEN * 64];
__device__ __align__(128) __half g_Kh[(size_t)BH_N * S_LEN * 64];
__device__ __align__(128) __half g_Vh[(size_t)BH_N * S_LEN * 64];

// ---------------- pre-kernel: fp32 -> fp16 (Q scaled by 0.125*log2e) --------
__global__ void __launch_bounds__(256) cvt_pre(const float4* __restrict__ Q,
                                               const float4* __restrict__ K,
                                               const float4* __restrict__ V)
{
    const int PER = (int)((size_t)BH_N * S_LEN * 64 / 4);   // float4s per tensor
    int gid = blockIdx.x * 256 + threadIdx.x;
    int stride = gridDim.x * 256;
    for (int i = gid; i < 3 * PER; i += stride) {
        int t = i / PER, off = i - t * PER;
        const float4* src = (t == 0) ? Q : (t == 1) ? K : V;
        uint2* dst = (uint2*)((t == 0) ? g_Qh : (t == 1) ? g_Kh : g_Vh);
        float s = (t == 0) ? 0.125f * 1.44269504f : 1.0f;
        float4 v = src[off];
        __half2 h0 = __floats2half2_rn(v.x * s, v.y * s);
        __half2 h1 = __floats2half2_rn(v.z * s, v.w * s);
        uint2 w;
        w.x = *(uint32_t*)&h0;
        w.y = *(uint32_t*)&h1;
        dst[off] = w;
    }
}

// ---------------- helpers ----------------
__device__ __forceinline__ uint32_t smem_u32(const void* p){
    uint32_t a; asm("{ .reg .u64 t; cvta.to.shared.u64 t, %1; cvt.u32.u64 %0, t; }"
                    : "=r"(a) : "l"(p)); return a;
}
__device__ __forceinline__ void cpa16(uint32_t dst, const void* src){
    asm volatile("cp.async.cg.shared.global [%0], [%1], 16;" :: "r"(dst), "l"(src));
}
__device__ __forceinline__ void ldsm4(uint32_t& r0, uint32_t& r1, uint32_t& r2,
                                      uint32_t& r3, uint32_t a){
    asm volatile("ldmatrix.sync.aligned.m8n8.x4.shared.b16 {%0,%1,%2,%3}, [%4];"
                 : "=r"(r0), "=r"(r1), "=r"(r2), "=r"(r3) : "r"(a));
}
__device__ __forceinline__ void ldsm4t(uint32_t& r0, uint32_t& r1, uint32_t& r2,
                                       uint32_t& r3, uint32_t a){
    asm volatile("ldmatrix.sync.aligned.m8n8.x4.trans.shared.b16 {%0,%1,%2,%3}, [%4];"
                 : "=r"(r0), "=r"(r1), "=r"(r2), "=r"(r3) : "r"(a));
}
__device__ __forceinline__ void mma168(float* d, const uint32_t* a,
                                       uint32_t b0, uint32_t b1){
    asm volatile(
        "mma.sync.aligned.m16n8k16.row.col.f32.f16.f16.f32 "
        "{%0,%1,%2,%3}, {%4,%5,%6,%7}, {%8,%9}, {%0,%1,%2,%3};"
        : "+f"(d[0]), "+f"(d[1]), "+f"(d[2]), "+f"(d[3])
        : "r"(a[0]), "r"(a[1]), "r"(a[2]), "r"(a[3]), "r"(b0), "r"(b1));
}
__device__ __forceinline__ uint32_t exp2_h2(float lo, float hi){
    __half2 h = __floats2half2_rn(lo, hi);
    h = h2exp2(h);
    return *(uint32_t*)&h;
}

// stage one K tile + one V tile (fp16, 16KB each) into padded smem rows
__device__ __forceinline__ void stage_kv(uint32_t sb, int buf, int tid,
                                         const __half* gk, const __half* gv){
    #pragma unroll
    for (int i = 0; i < 4; i++){
        int id = tid + 256 * i;                       // 0..1023 : row=id>>3, chunk=id&7
        uint32_t d = sb + KOFF + buf * TILEB + (id >> 3) * ROWB + (id & 7) * 16;
        cpa16(d, gk + (id >> 3) * 64 + (id & 7) * 8);
    }
    #pragma unroll
    for (int i = 0; i < 4; i++){
        int id = tid + 256 * i;
        uint32_t d = sb + VOFF + buf * TILEB + (id >> 3) * ROWB + (id & 7) * 16;
        cpa16(d, gv + (id >> 3) * 64 + (id & 7) * 8);
    }
    asm volatile("cp.async.commit_group;" ::: "memory");
}

// ---------------- main kernel ----------------
__global__ void __launch_bounds__(256, 1)
fa_mma(float* __restrict__ O)
{
    extern __shared__ char smraw[];
    const uint32_t sb = smem_u32(smraw);
    const int tid  = threadIdx.x;
    const int lane = tid & 31;
    const int w    = tid >> 5;                 // warp 0..7, owns q rows 16w..16w+15
    const int bh   = blockIdx.x >> 5;
    const int qt   = blockIdx.x & 31;

    const __half* gq = g_Qh + ((size_t)bh * S_LEN + (size_t)qt * 128) * 64;
    const __half* gk = g_Kh + (size_t)bh * S_LEN * 64;
    const __half* gv = g_Vh + (size_t)bh * S_LEN * 64;

    // ones-column (col 64 = 1.0, cols 65-71 = 0) in both V buffers, chunk 8.
    {
        int b = tid >> 7, row = tid & 127;
        uint32_t a = sb + VOFF + b * TILEB + row * ROWB + 128;
        asm volatile("st.shared.v4.b32 [%0], {%1,%2,%3,%4};"
                     :: "r"(a), "r"(0x00003C00u), "r"(0u), "r"(0u), "r"(0u));
    }

    // stage Q tile + KV tile 0 (group 0)
    #pragma unroll
    for (int i = 0; i < 4; i++){
        int id = tid + 256 * i;
        uint32_t d = sb + QOFF + (id >> 3) * ROWB + (id & 7) * 16;
        cpa16(d, gq + (id >> 3) * 64 + (id & 7) * 8);
    }
    stage_kv(sb, 0, tid, gk, gv);
    asm volatile("cp.async.wait_group 0;" ::: "memory");
    __syncthreads();

    // Q A-fragments (persist whole kernel): k-step k covers d 16k..16k+15
    uint32_t qA[4][4];
    {
        int qrow = 16 * w + (lane & 15);
        int qc   = lane >> 4;
        #pragma unroll
        for (int k = 0; k < 4; k++)
            ldsm4(qA[k][0], qA[k][1], qA[k][2], qA[k][3],
                  sb + QOFF + qrow * ROWB + (2 * k + qc) * 16);
    }

    // ldmatrix lane bases
    const int rbK = (lane & 7) + ((lane >> 4) << 3);   // K (non-trans) row base
    const int cbK = (lane >> 3) & 1;                   // K chunk bit
    const int rbV = (lane & 7) + (((lane >> 3) & 1) << 3); // V (trans) row base
    const int cbV = lane >> 4;                         // V chunk bit

    float o[9][4];                                      // 8 O tiles + ssum tile
    #pragma unroll
    for (int t = 0; t < 9; t++)
        #pragma unroll
        for (int c = 0; c < 4; c++) o[t][c] = 0.0f;
    float m1 = -INFINITY, m2 = -INFINITY;

    for (int kt = 0; kt < NKT; kt++){
        const int buf = kt & 1;
        __syncthreads();                                // all warps done with buf^1
        if (kt + 1 < NKT){
            stage_kv(sb, buf ^ 1, tid, gk + (size_t)(kt + 1) * 8192,
                                       gv + (size_t)(kt + 1) * 8192);
            asm volatile("cp.async.wait_group 1;" ::: "memory");
        } else {
            asm volatile("cp.async.wait_group 0;" ::: "memory");
        }
        __syncthreads();

        const uint32_t kbuf = sb + KOFF + buf * TILEB;
        const uint32_t vbuf = sb + VOFF + buf * TILEB;

        // ---- MMA1: S = Q @ K^T (16x128 per warp) ----
        float acc[16][4];
        #pragma unroll
        for (int t = 0; t < 16; t++)
            #pragma unroll
            for (int c = 0; c < 4; c++) acc[t][c] = 0.0f;

        const uint32_t kbase = kbuf + rbK * ROWB + cbK * 16;
        #pragma unroll
        for (int j4 = 0; j4 < 8; j4++){
            #pragma unroll
            for (int k = 0; k < 4; k++){
                uint32_t b0, b1, b2, b3;
                ldsm4(b0, b1, b2, b3, kbase + j4 * (16 * ROWB) + k * 32);
                mma168(acc[2 * j4],     qA[k], b0, b1);
                mma168(acc[2 * j4 + 1], qA[k], b2, b3);
            }
        }

        // ---- softmax (base-2 domain, warp-local) ----
        float mx1 = -INFINITY, mx2 = -INFINITY;
        #pragma unroll
        for (int t = 0; t < 16; t++){
            mx1 = fmaxf(mx1, fmaxf(acc[t][0], acc[t][1]));
            mx2 = fmaxf(mx2, fmaxf(acc[t][2], acc[t][3]));
        }
        mx1 = fmaxf(mx1, __shfl_xor_sync(0xffffffffu, mx1, 1));
        mx1 = fmaxf(mx1, __shfl_xor_sync(0xffffffffu, mx1, 2));
        mx2 = fmaxf(mx2, __shfl_xor_sync(0xffffffffu, mx2, 1));
        mx2 = fmaxf(mx2, __shfl_xor_sync(0xffffffffu, mx2, 2));

        const float nm1 = fmaxf(m1, mx1), nm2 = fmaxf(m2, mx2);
        const float adj1 = mx1 - 2.0f * nm1, adj2 = mx2 - 2.0f * nm2;
        const float osc1 = exp2f(m1 - nm1), osc2 = exp2f(m2 - nm2);
        m1 = nm1; m2 = nm2;

        // rescale O (incl. running ssum tile 8) by old_scale
        #pragma unroll
        for (int t = 0; t < 9; t++){
            o[t][0] *= osc1; o[t][1] *= osc1;
            o[t][2] *= osc2; o[t][3] *= osc2;
        }

        // P = exp2(s + adj) as fp16 A-fragments
        uint32_t pl[16], ph[16];
        #pragma unroll
        for (int t = 0; t < 16; t++){
            pl[t] = exp2_h2(acc[t][0] + adj1, acc[t][1] + adj1);
            ph[t] = exp2_h2(acc[t][2] + adj2, acc[t][3] + adj2);
        }

        // ---- MMA2: O += P @ [V | 1] (16x72 per warp; tile 8 = rowsum) ----
        const uint32_t vrow = vbuf + rbV * ROWB;
        #pragma unroll
        for (int kk = 0; kk < 8; kk++){
            uint32_t aA[4] = { pl[2 * kk], ph[2 * kk], pl[2 * kk + 1], ph[2 * kk + 1] };
            #pragma unroll
            for (int j4 = 0; j4 < 5; j4++){
                int chunk = (j4 == 4) ? 8 : (2 * j4 + cbV);
                uint32_t b0, b1, b2, b3;
                ldsm4t(b0, b1, b2, b3, vrow + kk * (16 * ROWB) + chunk * 16);
                mma168(o[2 * j4], aA, b0, b1);
                if (j4 < 4) mma168(o[2 * j4 + 1], aA, b2, b3);
            }
        }
    }

    // ---- epilogue: divide by ssum, write fp32 ----
    float sum1 = __shfl_sync(0xffffffffu, o[8][0], lane & ~3);
    float sum2 = __shfl_sync(0xffffffffu, o[8][2], lane & ~3);
    const float inv1 = 1.0f / sum1, inv2 = 1.0f / sum2;

    const int r1 = 16 * w + (lane >> 2);
    float* Ob = O + ((size_t)bh * S_LEN + (size_t)qt * 128) * 64;
    #pragma unroll
    for (int t = 0; t < 8; t++){
        int col = 8 * t + (lane & 3) * 2;
        *(float2*)(Ob + (size_t)r1 * 64 + col) =
            make_float2(o[t][0] * inv1, o[t][1] * inv1);
        *(float2*)(Ob + (size_t)(r1 + 8) * 64 + col) =
            make_float2(o[t][2] * inv2, o[t][3] * inv2);
    }
}

extern "C" void kernel_launch(void* const* d_in, const int* in_sizes, int n_in,
                              void* d_out, int out_size)
{
    const float4* Q = (const float4*)d_in[0];
    const float4* K = (const float4*)d_in[1];
    const float4* V = (const float4*)d_in[2];
    float* Ot = (float*)d_out;

    cudaFuncSetAttribute(fa_mma, cudaFuncAttributeMaxDynamicSharedMemorySize, SMEM_MAIN);
    cvt_pre<<<9216, 256>>>(Q, K, V);
    fa_mma<<<BH_N * NKT, 256, SMEM_MAIN>>>(Ot);
}

// round 6
// speedup vs baseline: 6.5224x; 1.2051x over previous
#include <cuda_runtime.h>
#include <cuda_fp16.h>
#include <cstdint>

// FlashAttention B=4,H=12,S=4096,D=64, TILE=128, fp32 in/out.
// mma.sync m16n8k16 fp16 (plain sm_103 target — tcgen05 unavailable).
// Reference recurrence kept exactly: p = exp(s + mx - 2*nm),
// O = O*exp(m-nm) + P@V, ssum = ssum*exp(m-nm) + rowsum(P).
// Base-2 softmax domain (Q pre-scaled by 0.125*log2 e).
//
// R6: 2 CTAs/SM (128 thr, 64 q-rows each) for cross-CTA phase overlap,
// 128B rows + XOR swizzle (72KB smem), constant-register ones B-fragment
// for the rowsum MMA, single __syncthreads per kv-iteration.

#define S_LEN 4096
#define NKT   32
#define BH_N  48

#define TILEB 16384          // 128 rows x 128 bytes
#define QOFF  0              // 64 rows x 128B = 8KB
#define KOFF  8192
#define VOFF  (8192 + 2*16384)
#define SMEM_MAIN (8192 + 4*16384)   // 73728

// fp16 pre-converted tensors
__device__ __align__(128) __half g_Qh[(size_t)BH_N * S_LEN * 64];
__device__ __align__(128) __half g_Kh[(size_t)BH_N * S_LEN * 64];
__device__ __align__(128) __half g_Vh[(size_t)BH_N * S_LEN * 64];

// ---------------- pre-kernel: fp32 -> fp16 (Q scaled by 0.125*log2e) --------
__global__ void __launch_bounds__(256) cvt_pre(const float4* __restrict__ Q,
                                               const float4* __restrict__ K,
                                               const float4* __restrict__ V)
{
    const int PER = (int)((size_t)BH_N * S_LEN * 64 / 4);
    int gid = blockIdx.x * 256 + threadIdx.x;
    int stride = gridDim.x * 256;
    for (int i = gid; i < 3 * PER; i += stride) {
        int t = i / PER, off = i - t * PER;
        const float4* src = (t == 0) ? Q : (t == 1) ? K : V;
        uint2* dst = (uint2*)((t == 0) ? g_Qh : (t == 1) ? g_Kh : g_Vh);
        float s = (t == 0) ? 0.125f * 1.44269504f : 1.0f;
        float4 v = src[off];
        __half2 h0 = __floats2half2_rn(v.x * s, v.y * s);
        __half2 h1 = __floats2half2_rn(v.z * s, v.w * s);
        uint2 w;
        w.x = *(uint32_t*)&h0;
        w.y = *(uint32_t*)&h1;
        dst[off] = w;
    }
}

// ---------------- helpers ----------------
__device__ __forceinline__ uint32_t smem_u32(const void* p){
    uint32_t a; asm("{ .reg .u64 t; cvta.to.shared.u64 t, %1; cvt.u32.u64 %0, t; }"
                    : "=r"(a) : "l"(p)); return a;
}
__device__ __forceinline__ void cpa16(uint32_t dst, const void* src){
    asm volatile("cp.async.cg.shared.global [%0], [%1], 16;" :: "r"(dst), "l"(src));
}
__device__ __forceinline__ void ldsm4(uint32_t& r0, uint32_t& r1, uint32_t& r2,
                                      uint32_t& r3, uint32_t a){
    asm volatile("ldmatrix.sync.aligned.m8n8.x4.shared.b16 {%0,%1,%2,%3}, [%4];"
                 : "=r"(r0), "=r"(r1), "=r"(r2), "=r"(r3) : "r"(a));
}
__device__ __forceinline__ void ldsm4t(uint32_t& r0, uint32_t& r1, uint32_t& r2,
                                       uint32_t& r3, uint32_t a){
    asm volatile("ldmatrix.sync.aligned.m8n8.x4.trans.shared.b16 {%0,%1,%2,%3}, [%4];"
                 : "=r"(r0), "=r"(r1), "=r"(r2), "=r"(r3) : "r"(a));
}
__device__ __forceinline__ void mma168(float* d, const uint32_t* a,
                                       uint32_t b0, uint32_t b1){
    asm volatile(
        "mma.sync.aligned.m16n8k16.row.col.f32.f16.f16.f32 "
        "{%0,%1,%2,%3}, {%4,%5,%6,%7}, {%8,%9}, {%0,%1,%2,%3};"
        : "+f"(d[0]), "+f"(d[1]), "+f"(d[2]), "+f"(d[3])
        : "r"(a[0]), "r"(a[1]), "r"(a[2]), "r"(a[3]), "r"(b0), "r"(b1));
}
__device__ __forceinline__ uint32_t exp2_h2(float lo, float hi){
    __half2 h = __floats2half2_rn(lo, hi);
    h = h2exp2(h);
    return *(uint32_t*)&h;
}

// stage one K tile + one V tile (fp16, 16KB each), 128 threads, XOR swizzle
__device__ __forceinline__ void stage_kv(uint32_t sb, int buf, int tid,
                                         const __half* gk, const __half* gv){
    #pragma unroll
    for (int i = 0; i < 8; i++){
        int id = tid + 128 * i;                  // 0..1023: row=id>>3, chunk=id&7
        int row = id >> 3, c = id & 7;
        uint32_t d = sb + KOFF + buf * TILEB + row * 128 + ((c ^ (row & 7)) << 4);
        cpa16(d, gk + row * 64 + c * 8);
    }
    #pragma unroll
    for (int i = 0; i < 8; i++){
        int id = tid + 128 * i;
        int row = id >> 3, c = id & 7;
        uint32_t d = sb + VOFF + buf * TILEB + row * 128 + ((c ^ (row & 7)) << 4);
        cpa16(d, gv + row * 64 + c * 8);
    }
    asm volatile("cp.async.commit_group;" ::: "memory");
}

// ---------------- main kernel: 128 threads, 64 q-rows per CTA ----------------
__global__ void __launch_bounds__(128, 2)
fa_mma(float* __restrict__ O)
{
    extern __shared__ char smraw[];
    const uint32_t sb = smem_u32(smraw);
    const int tid  = threadIdx.x;
    const int lane = tid & 31;
    const int w    = tid >> 5;                 // warp 0..3 owns q rows 16w..16w+15
    const int bh   = blockIdx.x >> 6;
    const int qt   = blockIdx.x & 63;          // 64-row q tiles

    const __half* gq = g_Qh + ((size_t)bh * S_LEN + (size_t)qt * 64) * 64;
    const __half* gk = g_Kh + (size_t)bh * S_LEN * 64;
    const __half* gv = g_Vh + (size_t)bh * S_LEN * 64;

    const uint32_t xk = (uint32_t)(lane & 7) << 4;   // swizzle key per lane

    // stage Q (8KB) + KV tile 0
    #pragma unroll
    for (int i = 0; i < 4; i++){
        int id = tid + 128 * i;                 // 0..511: row=id>>3 (0..63)
        int row = id >> 3, c = id & 7;
        uint32_t d = sb + QOFF + row * 128 + ((c ^ (row & 7)) << 4);
        cpa16(d, gq + row * 64 + c * 8);
    }
    stage_kv(sb, 0, tid, gk, gv);
    asm volatile("cp.async.wait_group 0;" ::: "memory");
    __syncthreads();

    // Q A-fragments (persist): k-step k covers d 16k..16k+15
    uint32_t qA[4][4];
    {
        int qrow = 16 * w + (lane & 15);
        int qc   = lane >> 4;
        #pragma unroll
        for (int k = 0; k < 4; k++)
            ldsm4(qA[k][0], qA[k][1], qA[k][2], qA[k][3],
                  sb + QOFF + qrow * 128 + ((((2 * k + qc) << 4)) ^ xk));
    }

    // ldmatrix lane row bases
    const int rbK = (lane & 7) + ((lane >> 4) << 3);       // K (non-trans)
    const int cbK = (lane >> 3) & 1;
    const int rbV = (lane & 7) + (((lane >> 3) & 1) << 3); // V (trans)
    const int cbV = lane >> 4;

    // constant B-fragment of the ones-column (n==0 column all 1.0)
    const uint32_t bone = (lane < 4) ? 0x3C003C00u : 0u;

    float o[9][4];                                   // 8 O tiles + rowsum tile
    #pragma unroll
    for (int t = 0; t < 9; t++)
        #pragma unroll
        for (int c = 0; c < 4; c++) o[t][c] = 0.0f;
    float m1 = -INFINITY, m2 = -INFINITY;

    for (int kt = 0; kt < NKT; kt++){
        const int buf = kt & 1;
        if (kt + 1 < NKT)
            stage_kv(sb, buf ^ 1, tid, gk + (size_t)(kt + 1) * 8192,
                                       gv + (size_t)(kt + 1) * 8192);

        const uint32_t kbuf = sb + KOFF + buf * TILEB;
        const uint32_t vbuf = sb + VOFF + buf * TILEB;

        // ---- MMA1: S = Q @ K^T (16x128 per warp) ----
        float acc[16][4];
        #pragma unroll
        for (int t = 0; t < 16; t++)
            #pragma unroll
            for (int c = 0; c < 4; c++) acc[t][c] = 0.0f;

        #pragma unroll
        for (int j4 = 0; j4 < 8; j4++){
            const uint32_t krow = kbuf + (rbK + j4 * 16) * 128;
            #pragma unroll
            for (int k = 0; k < 4; k++){
                uint32_t b0, b1, b2, b3;
                ldsm4(b0, b1, b2, b3, krow + ((((2 * k + cbK) << 4)) ^ xk));
                mma168(acc[2 * j4],     qA[k], b0, b1);
                mma168(acc[2 * j4 + 1], qA[k], b2, b3);
            }
        }

        // ---- softmax (base-2 domain, warp-local) ----
        float mx1 = -INFINITY, mx2 = -INFINITY;
        #pragma unroll
        for (int t = 0; t < 16; t++){
            mx1 = fmaxf(mx1, fmaxf(acc[t][0], acc[t][1]));
            mx2 = fmaxf(mx2, fmaxf(acc[t][2], acc[t][3]));
        }
        mx1 = fmaxf(mx1, __shfl_xor_sync(0xffffffffu, mx1, 1));
        mx1 = fmaxf(mx1, __shfl_xor_sync(0xffffffffu, mx1, 2));
        mx2 = fmaxf(mx2, __shfl_xor_sync(0xffffffffu, mx2, 1));
        mx2 = fmaxf(mx2, __shfl_xor_sync(0xffffffffu, mx2, 2));

        const float nm1 = fmaxf(m1, mx1), nm2 = fmaxf(m2, mx2);
        const float adj1 = mx1 - 2.0f * nm1, adj2 = mx2 - 2.0f * nm2;
        const float osc1 = exp2f(m1 - nm1), osc2 = exp2f(m2 - nm2);
        m1 = nm1; m2 = nm2;

        #pragma unroll
        for (int t = 0; t < 9; t++){
            o[t][0] *= osc1; o[t][1] *= osc1;
            o[t][2] *= osc2; o[t][3] *= osc2;
        }

        // P = exp2(s + adj) as fp16 A-fragments
        uint32_t pl[16], ph[16];
        #pragma unroll
        for (int t = 0; t < 16; t++){
            pl[t] = exp2_h2(acc[t][0] + adj1, acc[t][1] + adj1);
            ph[t] = exp2_h2(acc[t][2] + adj2, acc[t][3] + adj2);
        }

        // ---- MMA2: O += P @ V ; rowsum via constant ones B-fragment ----
        #pragma unroll
        for (int kk = 0; kk < 8; kk++){
            uint32_t aA[4] = { pl[2 * kk], ph[2 * kk], pl[2 * kk + 1], ph[2 * kk + 1] };
            const uint32_t vrow = vbuf + (kk * 16 + rbV) * 128;
            #pragma unroll
            for (int j4 = 0; j4 < 4; j4++){
                uint32_t b0, b1, b2, b3;
                ldsm4t(b0, b1, b2, b3, vrow + ((((2 * j4 + cbV) << 4)) ^ xk));
                mma168(o[2 * j4],     aA, b0, b1);
                mma168(o[2 * j4 + 1], aA, b2, b3);
            }
            mma168(o[8], aA, bone, bone);            // running row-sum
        }

        // kt+1 data must be resident before next iter reads it
        asm volatile("cp.async.wait_group 0;" ::: "memory");
        __syncthreads();
    }

    // ---- epilogue: divide by ssum, write fp32 ----
    float sum1 = __shfl_sync(0xffffffffu, o[8][0], lane & ~3);
    float sum2 = __shfl_sync(0xffffffffu, o[8][2], lane & ~3);
    const float inv1 = 1.0f / sum1, inv2 = 1.0f / sum2;

    const int r1 = 16 * w + (lane >> 2);
    float* Ob = O + ((size_t)bh * S_LEN + (size_t)qt * 64) * 64;
    #pragma unroll
    for (int t = 0; t < 8; t++){
        int col = 8 * t + (lane & 3) * 2;
        *(float2*)(Ob + (size_t)r1 * 64 + col) =
            make_float2(o[t][0] * inv1, o[t][1] * inv1);
        *(float2*)(Ob + (size_t)(r1 + 8) * 64 + col) =
            make_float2(o[t][2] * inv2, o[t][3] * inv2);
    }
}

extern "C" void kernel_launch(void* const* d_in, const int* in_sizes, int n_in,
                              void* d_out, int out_size)
{
    const float4* Q = (const float4*)d_in[0];
    const float4* K = (const float4*)d_in[1];
    const float4* V = (const float4*)d_in[2];
    float* Ot = (float*)d_out;

    cudaFuncSetAttribute(fa_mma, cudaFuncAttributeMaxDynamicSharedMemorySize, SMEM_MAIN);
    cvt_pre<<<9216, 256>>>(Q, K, V);
    fa_mma<<<BH_N * 64, 128, SMEM_MAIN>>>(Ot);
}

// round 7
// speedup vs baseline: 6.5434x; 1.0032x over previous
#include <cuda_runtime.h>
#include <cuda_fp16.h>
#include <cstdint>

// FlashAttention B=4,H=12,S=4096,D=64, TILE=128, fp32 in/out.
// mma.sync m16n8k16 fp16 (plain sm_103 target — tcgen05 unavailable).
// Reference recurrence kept exactly: p = exp(s + mx - 2*nm),
// O = O*exp(m-nm) + P@V, ssum = ssum*exp(m-nm) + rowsum(P).
// Base-2 softmax domain (Q pre-scaled by 0.125*log2 e).
//
// R7: interleave softmax with tensor work —
//  - row-max partials fused into the MMA1 n-tile loop
//  - exp -> fp16 P fragments computed just-in-time inside the MMA2 k-loop
//  - O-rescale skipped when the running max is unchanged (osc == 1)

#define S_LEN 4096
#define NKT   32
#define BH_N  48

#define TILEB 16384          // 128 rows x 128 bytes
#define QOFF  0              // 64 rows x 128B = 8KB
#define KOFF  8192
#define VOFF  (8192 + 2*16384)
#define SMEM_MAIN (8192 + 4*16384)   // 73728

__device__ __align__(128) __half g_Qh[(size_t)BH_N * S_LEN * 64];
__device__ __align__(128) __half g_Kh[(size_t)BH_N * S_LEN * 64];
__device__ __align__(128) __half g_Vh[(size_t)BH_N * S_LEN * 64];

// ---------------- pre-kernel: fp32 -> fp16 (Q scaled by 0.125*log2e) --------
__global__ void __launch_bounds__(256) cvt_pre(const float4* __restrict__ Q,
                                               const float4* __restrict__ K,
                                               const float4* __restrict__ V)
{
    const int PER = (int)((size_t)BH_N * S_LEN * 64 / 4);
    int gid = blockIdx.x * 256 + threadIdx.x;
    int stride = gridDim.x * 256;
    for (int i = gid; i < 3 * PER; i += stride) {
        int t = i / PER, off = i - t * PER;
        const float4* src = (t == 0) ? Q : (t == 1) ? K : V;
        uint2* dst = (uint2*)((t == 0) ? g_Qh : (t == 1) ? g_Kh : g_Vh);
        float s = (t == 0) ? 0.125f * 1.44269504f : 1.0f;
        float4 v = src[off];
        __half2 h0 = __floats2half2_rn(v.x * s, v.y * s);
        __half2 h1 = __floats2half2_rn(v.z * s, v.w * s);
        uint2 w;
        w.x = *(uint32_t*)&h0;
        w.y = *(uint32_t*)&h1;
        dst[off] = w;
    }
}

// ---------------- helpers ----------------
__device__ __forceinline__ uint32_t smem_u32(const void* p){
    uint32_t a; asm("{ .reg .u64 t; cvta.to.shared.u64 t, %1; cvt.u32.u64 %0, t; }"
                    : "=r"(a) : "l"(p)); return a;
}
__device__ __forceinline__ void cpa16(uint32_t dst, const void* src){
    asm volatile("cp.async.cg.shared.global [%0], [%1], 16;" :: "r"(dst), "l"(src));
}
__device__ __forceinline__ void ldsm4(uint32_t& r0, uint32_t& r1, uint32_t& r2,
                                      uint32_t& r3, uint32_t a){
    asm volatile("ldmatrix.sync.aligned.m8n8.x4.shared.b16 {%0,%1,%2,%3}, [%4];"
                 : "=r"(r0), "=r"(r1), "=r"(r2), "=r"(r3) : "r"(a));
}
__device__ __forceinline__ void ldsm4t(uint32_t& r0, uint32_t& r1, uint32_t& r2,
                                       uint32_t& r3, uint32_t a){
    asm volatile("ldmatrix.sync.aligned.m8n8.x4.trans.shared.b16 {%0,%1,%2,%3}, [%4];"
                 : "=r"(r0), "=r"(r1), "=r"(r2), "=r"(r3) : "r"(a));
}
__device__ __forceinline__ void mma168(float* d, const uint32_t* a,
                                       uint32_t b0, uint32_t b1){
    asm volatile(
        "mma.sync.aligned.m16n8k16.row.col.f32.f16.f16.f32 "
        "{%0,%1,%2,%3}, {%4,%5,%6,%7}, {%8,%9}, {%0,%1,%2,%3};"
        : "+f"(d[0]), "+f"(d[1]), "+f"(d[2]), "+f"(d[3])
        : "r"(a[0]), "r"(a[1]), "r"(a[2]), "r"(a[3]), "r"(b0), "r"(b1));
}
// exp2 of (lo+adj, hi+adj): fp32 adds, single fp16 rounding, f16x2 MUFU
__device__ __forceinline__ uint32_t exp2_h2(float lo, float hi, float adj){
    __half2 h = __floats2half2_rn(lo + adj, hi + adj);
    h = h2exp2(h);
    return *(uint32_t*)&h;
}

// stage one K tile + one V tile (fp16, 16KB each), 128 threads, XOR swizzle
__device__ __forceinline__ void stage_kv(uint32_t sb, int buf, int tid,
                                         const __half* gk, const __half* gv){
    #pragma unroll
    for (int i = 0; i < 8; i++){
        int id = tid + 128 * i;
        int row = id >> 3, c = id & 7;
        uint32_t d = sb + KOFF + buf * TILEB + row * 128 + ((c ^ (row & 7)) << 4);
        cpa16(d, gk + row * 64 + c * 8);
    }
    #pragma unroll
    for (int i = 0; i < 8; i++){
        int id = tid + 128 * i;
        int row = id >> 3, c = id & 7;
        uint32_t d = sb + VOFF + buf * TILEB + row * 128 + ((c ^ (row & 7)) << 4);
        cpa16(d, gv + row * 64 + c * 8);
    }
    asm volatile("cp.async.commit_group;" ::: "memory");
}

// ---------------- main kernel: 128 threads, 64 q-rows per CTA ----------------
__global__ void __launch_bounds__(128, 2)
fa_mma(float* __restrict__ O)
{
    extern __shared__ char smraw[];
    const uint32_t sb = smem_u32(smraw);
    const int tid  = threadIdx.x;
    const int lane = tid & 31;
    const int w    = tid >> 5;
    const int bh   = blockIdx.x >> 6;
    const int qt   = blockIdx.x & 63;

    const __half* gq = g_Qh + ((size_t)bh * S_LEN + (size_t)qt * 64) * 64;
    const __half* gk = g_Kh + (size_t)bh * S_LEN * 64;
    const __half* gv = g_Vh + (size_t)bh * S_LEN * 64;

    const uint32_t xk = (uint32_t)(lane & 7) << 4;

    // stage Q (8KB) + KV tile 0
    #pragma unroll
    for (int i = 0; i < 4; i++){
        int id = tid + 128 * i;
        int row = id >> 3, c = id & 7;
        uint32_t d = sb + QOFF + row * 128 + ((c ^ (row & 7)) << 4);
        cpa16(d, gq + row * 64 + c * 8);
    }
    stage_kv(sb, 0, tid, gk, gv);
    asm volatile("cp.async.wait_group 0;" ::: "memory");
    __syncthreads();

    // Q A-fragments (persist)
    uint32_t qA[4][4];
    {
        int qrow = 16 * w + (lane & 15);
        int qc   = lane >> 4;
        #pragma unroll
        for (int k = 0; k < 4; k++)
            ldsm4(qA[k][0], qA[k][1], qA[k][2], qA[k][3],
                  sb + QOFF + qrow * 128 + ((((2 * k + qc) << 4)) ^ xk));
    }

    const int rbK = (lane & 7) + ((lane >> 4) << 3);
    const int cbK = (lane >> 3) & 1;
    const int rbV = (lane & 7) + (((lane >> 3) & 1) << 3);
    const int cbV = lane >> 4;
    const uint32_t bone = (lane < 4) ? 0x3C003C00u : 0u;

    float o[9][4];
    #pragma unroll
    for (int t = 0; t < 9; t++)
        #pragma unroll
        for (int c = 0; c < 4; c++) o[t][c] = 0.0f;
    float m1 = -INFINITY, m2 = -INFINITY;

    for (int kt = 0; kt < NKT; kt++){
        const int buf = kt & 1;
        if (kt + 1 < NKT)
            stage_kv(sb, buf ^ 1, tid, gk + (size_t)(kt + 1) * 8192,
                                       gv + (size_t)(kt + 1) * 8192);

        const uint32_t kbuf = sb + KOFF + buf * TILEB;
        const uint32_t vbuf = sb + VOFF + buf * TILEB;

        // ---- MMA1 with fused partial row-max ----
        float acc[16][4];
        #pragma unroll
        for (int t = 0; t < 16; t++)
            #pragma unroll
            for (int c = 0; c < 4; c++) acc[t][c] = 0.0f;

        float mx1 = -INFINITY, mx2 = -INFINITY;
        #pragma unroll
        for (int j4 = 0; j4 < 8; j4++){
            const uint32_t krow = kbuf + (rbK + j4 * 16) * 128;
            #pragma unroll
            for (int k = 0; k < 4; k++){
                uint32_t b0, b1, b2, b3;
                ldsm4(b0, b1, b2, b3, krow + ((((2 * k + cbK) << 4)) ^ xk));
                mma168(acc[2 * j4],     qA[k], b0, b1);
                mma168(acc[2 * j4 + 1], qA[k], b2, b3);
            }
            // partial max for the two tiles just finished (rides under next j4)
            mx1 = fmaxf(mx1, fmaxf(fmaxf(acc[2*j4][0], acc[2*j4][1]),
                                   fmaxf(acc[2*j4+1][0], acc[2*j4+1][1])));
            mx2 = fmaxf(mx2, fmaxf(fmaxf(acc[2*j4][2], acc[2*j4][3]),
                                   fmaxf(acc[2*j4+1][2], acc[2*j4+1][3])));
        }

        mx1 = fmaxf(mx1, __shfl_xor_sync(0xffffffffu, mx1, 1));
        mx1 = fmaxf(mx1, __shfl_xor_sync(0xffffffffu, mx1, 2));
        mx2 = fmaxf(mx2, __shfl_xor_sync(0xffffffffu, mx2, 1));
        mx2 = fmaxf(mx2, __shfl_xor_sync(0xffffffffu, mx2, 2));

        const float nm1 = fmaxf(m1, mx1), nm2 = fmaxf(m2, mx2);
        const float adj1 = mx1 - 2.0f * nm1, adj2 = mx2 - 2.0f * nm2;
        const float osc1 = exp2f(m1 - nm1), osc2 = exp2f(m2 - nm2);

        // rescale only when a running max actually changed (osc != 1)
        if (__any_sync(0xffffffffu, (nm1 != m1) | (nm2 != m2))){
            #pragma unroll
            for (int t = 0; t < 9; t++){
                o[t][0] *= osc1; o[t][1] *= osc1;
                o[t][2] *= osc2; o[t][3] *= osc2;
            }
        }
        m1 = nm1; m2 = nm2;

        // ---- MMA2 with just-in-time exp: P fragments per k-step ----
        #pragma unroll
        for (int kk = 0; kk < 8; kk++){
            uint32_t aA[4];
            aA[0] = exp2_h2(acc[2*kk][0],   acc[2*kk][1],   adj1);
            aA[1] = exp2_h2(acc[2*kk][2],   acc[2*kk][3],   adj2);
            aA[2] = exp2_h2(acc[2*kk+1][0], acc[2*kk+1][1], adj1);
            aA[3] = exp2_h2(acc[2*kk+1][2], acc[2*kk+1][3], adj2);

            const uint32_t vrow = vbuf + (kk * 16 + rbV) * 128;
            #pragma unroll
            for (int j4 = 0; j4 < 4; j4++){
                uint32_t b0, b1, b2, b3;
                ldsm4t(b0, b1, b2, b3, vrow + ((((2 * j4 + cbV) << 4)) ^ xk));
                mma168(o[2 * j4],     aA, b0, b1);
                mma168(o[2 * j4 + 1], aA, b2, b3);
            }
            mma168(o[8], aA, bone, bone);            // running row-sum (fp32 accum)
        }

        asm volatile("cp.async.wait_group 0;" ::: "memory");
        __syncthreads();
    }

    // ---- epilogue ----
    float sum1 = __shfl_sync(0xffffffffu, o[8][0], lane & ~3);
    float sum2 = __shfl_sync(0xffffffffu, o[8][2], lane & ~3);
    const float inv1 = 1.0f / sum1, inv2 = 1.0f / sum2;

    const int r1 = 16 * w + (lane >> 2);
    float* Ob = O + ((size_t)bh * S_LEN + (size_t)qt * 64) * 64;
    #pragma unroll
    for (int t = 0; t < 8; t++){
        int col = 8 * t + (lane & 3) * 2;
        *(float2*)(Ob + (size_t)r1 * 64 + col) =
            make_float2(o[t][0] * inv1, o[t][1] * inv1);
        *(float2*)(Ob + (size_t)(r1 + 8) * 64 + col) =
            make_float2(o[t][2] * inv2, o[t][3] * inv2);
    }
}

extern "C" void kernel_launch(void* const* d_in, const int* in_sizes, int n_in,
                              void* d_out, int out_size)
{
    const float4* Q = (const float4*)d_in[0];
    const float4* K = (const float4*)d_in[1];
    const float4* V = (const float4*)d_in[2];
    float* Ot = (float*)d_out;

    cudaFuncSetAttribute(fa_mma, cudaFuncAttributeMaxDynamicSharedMemorySize, SMEM_MAIN);
    cvt_pre<<<9216, 256>>>(Q, K, V);
    fa_mma<<<BH_N * 64, 128, SMEM_MAIN>>>(Ot);
}

// round 8
// speedup vs baseline: 7.0189x; 1.0727x over previous
#include <cuda_runtime.h>
#include <cuda_fp16.h>
#include <cstdint>

// FlashAttention B=4,H=12,S=4096,D=64, TILE=128, fp32 in/out.
// mma.sync m16n8k16 fp16 (plain sm_103 target — tcgen05 unavailable).
// Reference recurrence kept exactly: p = exp(s + mx - 2*nm),
// O = O*exp(m-nm) + P@V, ssum = ssum*exp(m-nm) + rowsum(P).
// Base-2 softmax domain (Q pre-scaled by 0.125*log2 e).
//
// R8: 3 CTAs/SM (12 warps, 3 independent sync domains) to cover softmax
// dependency stalls. Register diet to fit 65536/384 = 170 regs/thread:
// bulk P conversion (acc dies before MMA2), hoisted swizzle-address
// constants, incremental pointer stepping, __launch_bounds__(128,3).

#define S_LEN 4096
#define NKT   32
#define BH_N  48

#define TILEB 16384          // 128 rows x 128 bytes
#define QOFF  0              // 64 rows x 128B = 8KB
#define KOFF  8192
#define VOFF  (8192 + 2*16384)
#define SMEM_MAIN (8192 + 4*16384)   // 73728

__device__ __align__(128) __half g_Qh[(size_t)BH_N * S_LEN * 64];
__device__ __align__(128) __half g_Kh[(size_t)BH_N * S_LEN * 64];
__device__ __align__(128) __half g_Vh[(size_t)BH_N * S_LEN * 64];

// ---------------- pre-kernel: fp32 -> fp16 (Q scaled by 0.125*log2e) --------
__global__ void __launch_bounds__(256) cvt_pre(const float4* __restrict__ Q,
                                               const float4* __restrict__ K,
                                               const float4* __restrict__ V)
{
    const int PER = (int)((size_t)BH_N * S_LEN * 64 / 4);
    int gid = blockIdx.x * 256 + threadIdx.x;
    int stride = gridDim.x * 256;
    for (int i = gid; i < 3 * PER; i += stride) {
        int t = i / PER, off = i - t * PER;
        const float4* src = (t == 0) ? Q : (t == 1) ? K : V;
        uint2* dst = (uint2*)((t == 0) ? g_Qh : (t == 1) ? g_Kh : g_Vh);
        float s = (t == 0) ? 0.125f * 1.44269504f : 1.0f;
        float4 v = src[off];
        __half2 h0 = __floats2half2_rn(v.x * s, v.y * s);
        __half2 h1 = __floats2half2_rn(v.z * s, v.w * s);
        uint2 w;
        w.x = *(uint32_t*)&h0;
        w.y = *(uint32_t*)&h1;
        dst[off] = w;
    }
}

// ---------------- helpers ----------------
__device__ __forceinline__ uint32_t smem_u32(const void* p){
    uint32_t a; asm("{ .reg .u64 t; cvta.to.shared.u64 t, %1; cvt.u32.u64 %0, t; }"
                    : "=r"(a) : "l"(p)); return a;
}
__device__ __forceinline__ void cpa16(uint32_t dst, const void* src){
    asm volatile("cp.async.cg.shared.global [%0], [%1], 16;" :: "r"(dst), "l"(src));
}
__device__ __forceinline__ void ldsm4(uint32_t& r0, uint32_t& r1, uint32_t& r2,
                                      uint32_t& r3, uint32_t a){
    asm volatile("ldmatrix.sync.aligned.m8n8.x4.shared.b16 {%0,%1,%2,%3}, [%4];"
                 : "=r"(r0), "=r"(r1), "=r"(r2), "=r"(r3) : "r"(a));
}
__device__ __forceinline__ void ldsm4t(uint32_t& r0, uint32_t& r1, uint32_t& r2,
                                       uint32_t& r3, uint32_t a){
    asm volatile("ldmatrix.sync.aligned.m8n8.x4.trans.shared.b16 {%0,%1,%2,%3}, [%4];"
                 : "=r"(r0), "=r"(r1), "=r"(r2), "=r"(r3) : "r"(a));
}
__device__ __forceinline__ void mma168(float* d, const uint32_t* a,
                                       uint32_t b0, uint32_t b1){
    asm volatile(
        "mma.sync.aligned.m16n8k16.row.col.f32.f16.f16.f32 "
        "{%0,%1,%2,%3}, {%4,%5,%6,%7}, {%8,%9}, {%0,%1,%2,%3};"
        : "+f"(d[0]), "+f"(d[1]), "+f"(d[2]), "+f"(d[3])
        : "r"(a[0]), "r"(a[1]), "r"(a[2]), "r"(a[3]), "r"(b0), "r"(b1));
}
__device__ __forceinline__ uint32_t exp2_h2(float lo, float hi, float adj){
    __half2 h = __floats2half2_rn(lo + adj, hi + adj);
    h = h2exp2(h);
    return *(uint32_t*)&h;
}

// stage one K tile + one V tile (fp16, 16KB each), 128 threads, XOR swizzle.
// Incremental addressing: one dst reg + one src pointer per stream.
__device__ __forceinline__ void stage_kv(uint32_t sb, int buf, int tid,
                                         const __half* gk, const __half* gv){
    const int row0 = tid >> 3, c = tid & 7;
    const uint32_t sw = (uint32_t)((c ^ (row0 & 7)) << 4);   // row&7 invariant (+16 steps)
    uint32_t dk = sb + KOFF + buf * TILEB + row0 * 128 + sw;
    uint32_t dv = sb + VOFF + buf * TILEB + row0 * 128 + sw;
    const __half* sk = gk + row0 * 64 + c * 8;
    const __half* sv = gv + row0 * 64 + c * 8;
    #pragma unroll
    for (int i = 0; i < 8; i++){
        cpa16(dk, sk); dk += 2048; sk += 1024;
        cpa16(dv, sv); dv += 2048; sv += 1024;
    }
    asm volatile("cp.async.commit_group;" ::: "memory");
}

// ---------------- main kernel: 128 threads, 64 q-rows, 3 CTAs/SM ------------
__global__ void __launch_bounds__(128, 3)
fa_mma(float* __restrict__ O)
{
    extern __shared__ char smraw[];
    const uint32_t sb = smem_u32(smraw);
    const int tid  = threadIdx.x;
    const int lane = tid & 31;
    const int w    = tid >> 5;
    const int bh   = blockIdx.x >> 6;
    const int qt   = blockIdx.x & 63;

    const __half* gq = g_Qh + ((size_t)bh * S_LEN + (size_t)qt * 64) * 64;
    const __half* gk = g_Kh + (size_t)bh * S_LEN * 64;
    const __half* gv = g_Vh + (size_t)bh * S_LEN * 64;

    const uint32_t xk = (uint32_t)(lane & 7) << 4;

    // stage Q (8KB) + KV tile 0
    {
        const int row0 = tid >> 3, c = tid & 7;
        const uint32_t sw = (uint32_t)((c ^ (row0 & 7)) << 4);
        uint32_t dq = sb + QOFF + row0 * 128 + sw;
        const __half* sq = gq + row0 * 64 + c * 8;
        #pragma unroll
        for (int i = 0; i < 4; i++){ cpa16(dq, sq); dq += 2048; sq += 1024; }
    }
    stage_kv(sb, 0, tid, gk, gv);
    asm volatile("cp.async.wait_group 0;" ::: "memory");
    __syncthreads();

    // Q A-fragments (persist)
    uint32_t qA[4][4];
    {
        int qrow = 16 * w + (lane & 15);
        int qc   = lane >> 4;
        uint32_t qb = sb + QOFF + qrow * 128;
        #pragma unroll
        for (int k = 0; k < 4; k++)
            ldsm4(qA[k][0], qA[k][1], qA[k][2], qA[k][3],
                  qb + ((uint32_t)((2 * k + qc) << 4) ^ xk));
    }

    // hoisted swizzled chunk offsets (invariant across kt)
    const int rbK = (lane & 7) + ((lane >> 4) << 3);
    const int cbK = (lane >> 3) & 1;
    const int rbV = (lane & 7) + (((lane >> 3) & 1) << 3);
    const int cbV = lane >> 4;
    uint32_t ckK[4], ckV[4];
    #pragma unroll
    for (int k = 0; k < 4; k++){
        ckK[k] = ((uint32_t)((2 * k + cbK) << 4)) ^ xk;
        ckV[k] = ((uint32_t)((2 * k + cbV) << 4)) ^ xk;
    }
    const uint32_t bone = (lane < 4) ? 0x3C003C00u : 0u;

    float o[9][4];
    #pragma unroll
    for (int t = 0; t < 9; t++)
        #pragma unroll
        for (int c = 0; c < 4; c++) o[t][c] = 0.0f;
    float m1 = -INFINITY, m2 = -INFINITY;

    for (int kt = 0; kt < NKT; kt++){
        const int buf = kt & 1;
        if (kt + 1 < NKT)
            stage_kv(sb, buf ^ 1, tid, gk + (size_t)(kt + 1) * 8192,
                                       gv + (size_t)(kt + 1) * 8192);

        // ---- MMA1 with fused partial row-max ----
        float acc[16][4];
        #pragma unroll
        for (int t = 0; t < 16; t++)
            #pragma unroll
            for (int c = 0; c < 4; c++) acc[t][c] = 0.0f;

        float mx1 = -INFINITY, mx2 = -INFINITY;
        {
            uint32_t krow = sb + KOFF + buf * TILEB + rbK * 128;
            #pragma unroll
            for (int j4 = 0; j4 < 8; j4++){
                #pragma unroll
                for (int k = 0; k < 4; k++){
                    uint32_t b0, b1, b2, b3;
                    ldsm4(b0, b1, b2, b3, krow + ckK[k]);
                    mma168(acc[2 * j4],     qA[k], b0, b1);
                    mma168(acc[2 * j4 + 1], qA[k], b2, b3);
                }
                krow += 2048;
                mx1 = fmaxf(mx1, fmaxf(fmaxf(acc[2*j4][0], acc[2*j4][1]),
                                       fmaxf(acc[2*j4+1][0], acc[2*j4+1][1])));
                mx2 = fmaxf(mx2, fmaxf(fmaxf(acc[2*j4][2], acc[2*j4][3]),
                                       fmaxf(acc[2*j4+1][2], acc[2*j4+1][3])));
            }
        }

        mx1 = fmaxf(mx1, __shfl_xor_sync(0xffffffffu, mx1, 1));
        mx1 = fmaxf(mx1, __shfl_xor_sync(0xffffffffu, mx1, 2));
        mx2 = fmaxf(mx2, __shfl_xor_sync(0xffffffffu, mx2, 1));
        mx2 = fmaxf(mx2, __shfl_xor_sync(0xffffffffu, mx2, 2));

        const float nm1 = fmaxf(m1, mx1), nm2 = fmaxf(m2, mx2);
        const float adj1 = mx1 - 2.0f * nm1, adj2 = mx2 - 2.0f * nm2;
        const float osc1 = exp2f(m1 - nm1), osc2 = exp2f(m2 - nm2);

        if (__any_sync(0xffffffffu, (nm1 != m1) | (nm2 != m2))){
            #pragma unroll
            for (int t = 0; t < 9; t++){
                o[t][0] *= osc1; o[t][1] *= osc1;
                o[t][2] *= osc2; o[t][3] *= osc2;
            }
        }
        m1 = nm1; m2 = nm2;

        // ---- bulk P conversion (acc dies here; pl/ph reuse its space) ----
        uint32_t pl[16], ph[16];
        #pragma unroll
        for (int t = 0; t < 16; t++){
            pl[t] = exp2_h2(acc[t][0], acc[t][1], adj1);
            ph[t] = exp2_h2(acc[t][2], acc[t][3], adj2);
        }

        // ---- MMA2: O += P @ V ; rowsum via constant ones B-fragment ----
        {
            uint32_t vrow = sb + VOFF + buf * TILEB + rbV * 128;
            #pragma unroll
            for (int kk = 0; kk < 8; kk++){
                uint32_t aA[4] = { pl[2*kk], ph[2*kk], pl[2*kk+1], ph[2*kk+1] };
                #pragma unroll
                for (int j4 = 0; j4 < 4; j4++){
                    uint32_t b0, b1, b2, b3;
                    ldsm4t(b0, b1, b2, b3, vrow + ckV[j4]);
                    mma168(o[2 * j4],     aA, b0, b1);
                    mma168(o[2 * j4 + 1], aA, b2, b3);
                }
                mma168(o[8], aA, bone, bone);
                vrow += 2048;
            }
        }

        asm volatile("cp.async.wait_group 0;" ::: "memory");
        __syncthreads();
    }

    // ---- epilogue ----
    float sum1 = __shfl_sync(0xffffffffu, o[8][0], lane & ~3);
    float sum2 = __shfl_sync(0xffffffffu, o[8][2], lane & ~3);
    const float inv1 = 1.0f / sum1, inv2 = 1.0f / sum2;

    const int r1 = 16 * w + (lane >> 2);
    float* Ob = O + ((size_t)bh * S_LEN + (size_t)qt * 64) * 64;
    #pragma unroll
    for (int t = 0; t < 8; t++){
        int col = 8 * t + (lane & 3) * 2;
        *(float2*)(Ob + (size_t)r1 * 64 + col) =
            make_float2(o[t][0] * inv1, o[t][1] * inv1);
        *(float2*)(Ob + (size_t)(r1 + 8) * 64 + col) =
            make_float2(o[t][2] * inv2, o[t][3] * inv2);
    }
}

extern "C" void kernel_launch(void* const* d_in, const int* in_sizes, int n_in,
                              void* d_out, int out_size)
{
    const float4* Q = (const float4*)d_in[0];
    const float4* K = (const float4*)d_in[1];
    const float4* V = (const float4*)d_in[2];
    float* Ot = (float*)d_out;

    cudaFuncSetAttribute(fa_mma, cudaFuncAttributeMaxDynamicSharedMemorySize, SMEM_MAIN);
    cvt_pre<<<9216, 256>>>(Q, K, V);
    fa_mma<<<BH_N * 64, 128, SMEM_MAIN>>>(Ot);
}